// round 16
// baseline (speedup 1.0000x reference)
#include <cuda_runtime.h>
#include <cuda_bf16.h>
#include <math.h>
#include <stdint.h>

#define BATCH      8
#define NPTS       16384
#define ROWS       (BATCH * NPTS)       // 131072
#define FIELD      512
#define OUT_DIM    515
#define TOPK       1024
#define CAND       1536                 // candidates per batch (margin 512)
#define CTOT       (BATCH * CAND)       // 12288
#define NCHUNK     16                   // FIELD / 32

// ---------------------------------------------------------------------------
// Scratch
// ---------------------------------------------------------------------------
__device__ __nv_bfloat16 g_X[(size_t)ROWS * FIELD];
__device__ __nv_bfloat16 g_H[(size_t)ROWS * FIELD];
__device__ __nv_bfloat16 g_W1t[FIELD * FIELD];      // [n][k] transposed
__device__ __nv_bfloat16 g_W2t[FIELD * FIELD];
__device__ float g_w2tail[3][FIELD];                // W2[:,512..514] transposed
__device__ float g_ssq_part[4][ROWS];               // per N-tile SS partials
__device__ float g_ssq[ROWS];                       // approx importance (SS)
__device__ int   g_cand[CTOT];                      // candidate global rows
__device__ int   g_cand_idx[CTOT];                  // candidate point idx
__device__ float g_Hex[(size_t)CTOT * FIELD];       // exact H (compact)
__device__ float g_Eex[(size_t)CTOT * OUT_DIM];     // exact E (compact)
__device__ float g_impex[CTOT];                     // exact importance
__device__ int   g_sel[BATCH * TOPK];               // compact pos of winners

extern __shared__ char dyn_smem[];   // gemms: 32KB; select: 64KB

// ---------------------------------------------------------------------------
// PTX helpers (base ISA: ldmatrix + mma.sync + cp.async, sm_80+)
// ---------------------------------------------------------------------------
__device__ __forceinline__ uint32_t smem_u32(const void* p)
{
    uint32_t a;
    asm("{ .reg .u64 t; cvta.to.shared.u64 t, %1; cvt.u32.u64 %0, t; }"
        : "=r"(a) : "l"(p));
    return a;
}
__device__ __forceinline__ void ldsm_x4(uint32_t* r, uint32_t addr)
{
    asm volatile("ldmatrix.sync.aligned.m8n8.x4.shared.b16 {%0,%1,%2,%3}, [%4];"
                 : "=r"(r[0]), "=r"(r[1]), "=r"(r[2]), "=r"(r[3]) : "r"(addr));
}
__device__ __forceinline__ void mma_bf16(float* c, const uint32_t* a, const uint32_t* b)
{
    asm volatile(
        "mma.sync.aligned.m16n8k16.row.col.f32.bf16.bf16.f32 "
        "{%0,%1,%2,%3}, {%4,%5,%6,%7}, {%8,%9}, {%0,%1,%2,%3};"
        : "+f"(c[0]), "+f"(c[1]), "+f"(c[2]), "+f"(c[3])
        : "r"(a[0]), "r"(a[1]), "r"(a[2]), "r"(a[3]), "r"(b[0]), "r"(b[1]));
}
__device__ __forceinline__ uint32_t sw64(uint32_t off)
{
    return off ^ ((off >> 3) & 0x30);
}
__device__ __forceinline__ void cp_async16(uint32_t sp, const void* gp)
{
    asm volatile("cp.async.cg.shared.global [%0], [%1], 16;"
                 :: "r"(sp), "l"(gp) : "memory");
}

// ---------------------------------------------------------------------------
// Exact-path math (bit-faithful to reference; proven in R3)
// ---------------------------------------------------------------------------
__device__ __forceinline__ float xla_erf_f32(float x)
{
    x = fminf(fmaxf(x, -4.0f), 4.0f);
    const float z = __fmul_rn(x, x);
    float p = fmaf(z, -2.72614225801306e-10f, 2.77068142495902e-08f);
    p = fmaf(z, p, -2.10102402082508e-06f);
    p = fmaf(z, p, -5.69250639462346e-05f);
    p = fmaf(z, p, -7.34990630326855e-04f);
    p = fmaf(z, p, -2.95459980854025e-03f);
    p = fmaf(z, p, -1.60960333262415e-02f);
    p = __fmul_rn(x, p);
    float q = fmaf(z, -1.45660718464996e-05f, -2.13374055278905e-04f);
    q = fmaf(z, q, -1.68282697438203e-03f);
    q = fmaf(z, q, -7.37332916720468e-03f);
    q = fmaf(z, q, -1.42647390514189e-02f);
    return __fdiv_rn(p, q);
}
__device__ __forceinline__ float xla_gelu(float v)
{
    const float t = __fdiv_rn(v, 1.4142135623730951f);
    const float s = __fadd_rn(xla_erf_f32(t), 1.0f);
    return __fmul_rn(__fmul_rn(v, s), 0.5f);
}

// ---------------------------------------------------------------------------
// Conversion / prep kernels (R13 structure: separate, full-grid)
// ---------------------------------------------------------------------------
__global__ __launch_bounds__(256) void conv_X_kernel(const float* __restrict__ dens)
{
    const size_t base = ((size_t)blockIdx.x * 256 + threadIdx.x) * 4;
    if (base >= (size_t)ROWS * FIELD) return;
    const float4 v = *reinterpret_cast<const float4*>(&dens[base]);
    __nv_bfloat16 h[4];
    h[0] = __float2bfloat16(v.x);
    h[1] = __float2bfloat16(v.y);
    h[2] = __float2bfloat16(v.z);
    h[3] = __float2bfloat16(v.w);
    *reinterpret_cast<uint2*>(&g_X[base]) = *reinterpret_cast<uint2*>(h);
}

__global__ __launch_bounds__(256) void conv_W_kernel(
    const float* __restrict__ W1, const float* __restrict__ W2)
{
    const int id = blockIdx.x * 256 + threadIdx.x;
    if (id >= FIELD * FIELD) return;
    const int n = id >> 9, k = id & 511;
    g_W1t[(size_t)n * FIELD + k] = __float2bfloat16(W1[(size_t)(2 + k) * FIELD + n]);
    g_W2t[(size_t)n * FIELD + k] = __float2bfloat16(W2[(size_t)k * OUT_DIM + n]);
    if (n < 3)
        g_w2tail[n][k] = W2[(size_t)k * OUT_DIM + 512 + n];
}

// ---------------------------------------------------------------------------
// Bulk GEMM (R13-proven config): CTA 128x128, BK=32 (16 K-chunks),
// 8 warps 2(m)x4(n), warp tile 64x32, single-pass bf16 mma,
// cp.async double-buffered (2 x 16KB stages).
// ---------------------------------------------------------------------------
#define STG_BYTES 16384

__device__ __forceinline__ void load_tile_async(
    uint32_t dst, const __nv_bfloat16* __restrict__ src,
    int row0, int k0, int tid)
{
#pragma unroll
    for (int s = tid; s < 512; s += 256) {
        const int r = s >> 2, seg = s & 3;
        cp_async16(dst + sw64(r * 64 + seg * 16),
                   &src[(size_t)(row0 + r) * FIELD + k0 + seg * 8]);
    }
}

__device__ __forceinline__ void bulk_mainloop_mma(
    const __nv_bfloat16* __restrict__ A, const __nv_bfloat16* __restrict__ B,
    int row0, int col0, float acc[4][4][4])
{
    const int tid  = threadIdx.x;
    const int wid  = tid >> 5, lane = tid & 31;
    const int wm   = wid >> 2, wn = wid & 3;
    const uint32_t sb = smem_u32(dyn_smem);

    const int a_row = (lane & 7) + ((lane >> 3) & 1) * 8;
    const int a_kof = ((lane >> 4) << 3);
    const int b_row = (lane & 7) + ((lane >> 4) << 3);
    const int b_kof = (((lane >> 3) & 1) << 3);

#pragma unroll
    for (int mf = 0; mf < 4; mf++)
#pragma unroll
        for (int nf = 0; nf < 4; nf++)
#pragma unroll
            for (int q = 0; q < 4; q++) acc[mf][nf][q] = 0.0f;

    {
        load_tile_async(sb +    0, A, row0, 0, tid);
        load_tile_async(sb + 8192, B, col0, 0, tid);
        asm volatile("cp.async.commit_group;" ::: "memory");
    }

    for (int c = 0; c < NCHUNK; c++) {
        if (c < NCHUNK - 1) {
            const uint32_t st = sb + ((c + 1) & 1) * STG_BYTES;
            const int k0 = (c + 1) * 32;
            load_tile_async(st +    0, A, row0, k0, tid);
            load_tile_async(st + 8192, B, col0, k0, tid);
            asm volatile("cp.async.commit_group;" ::: "memory");
            asm volatile("cp.async.wait_group 1;" ::: "memory");
        } else {
            asm volatile("cp.async.wait_group 0;" ::: "memory");
        }
        __syncthreads();

        const uint32_t st = sb + (c & 1) * STG_BYTES;
        const uint32_t aA = st, aB = st + 8192;

#pragma unroll
        for (int kk = 0; kk < 32; kk += 16) {
            uint32_t Af[4][4], Bf[2][4];
#pragma unroll
            for (int mf = 0; mf < 4; mf++) {
                const uint32_t off = sw64(
                    (uint32_t)((wm * 64 + mf * 16 + a_row) * 64 + (kk + a_kof) * 2));
                ldsm_x4(Af[mf], aA + off);
            }
#pragma unroll
            for (int pr = 0; pr < 2; pr++) {
                const uint32_t off = sw64(
                    (uint32_t)((wn * 32 + pr * 16 + b_row) * 64 + (kk + b_kof) * 2));
                ldsm_x4(Bf[pr], aB + off);
            }
#pragma unroll
            for (int mf = 0; mf < 4; mf++)
#pragma unroll
                for (int nf = 0; nf < 4; nf++)
                    mma_bf16(acc[mf][nf], Af[mf], &Bf[nf >> 1][(nf & 1) * 2]);
        }
        __syncthreads();
    }
}

__global__ __launch_bounds__(256)
void gemm1_bulk_kernel(const float* __restrict__ coords,
                       const float* __restrict__ W1,
                       const float* __restrict__ b1)
{
    const int col0 = blockIdx.x * 128, row0 = blockIdx.y * 128;
    const int wid  = threadIdx.x >> 5, lane = threadIdx.x & 31;
    const int wm   = wid >> 2, wn = wid & 3;
    const int mrow = lane >> 2, qcol = (lane & 3) * 2;

    float acc[4][4][4];
    bulk_mainloop_mma(g_X, g_W1t, row0, col0, acc);

#pragma unroll
    for (int mf = 0; mf < 4; mf++) {
        const int r0 = row0 + wm * 64 + mf * 16 + mrow;
        const int r1 = r0 + 8;
        const float c00 = coords[(size_t)r0 * 2], c01 = coords[(size_t)r0 * 2 + 1];
        const float c10 = coords[(size_t)r1 * 2], c11 = coords[(size_t)r1 * 2 + 1];
#pragma unroll
        for (int nf = 0; nf < 4; nf++) {
            const int n = col0 + wn * 32 + nf * 8 + qcol;
            const float w0a = W1[n],     w1a = W1[FIELD + n],     ba = b1[n];
            const float w0b = W1[n + 1], w1b = W1[FIELD + n + 1], bb = b1[n + 1];
            float v00 = xla_gelu(acc[mf][nf][0] + c00 * w0a + c01 * w1a + ba);
            float v01 = xla_gelu(acc[mf][nf][1] + c00 * w0b + c01 * w1b + bb);
            float v10 = xla_gelu(acc[mf][nf][2] + c10 * w0a + c11 * w1a + ba);
            float v11 = xla_gelu(acc[mf][nf][3] + c10 * w0b + c11 * w1b + bb);
            __nv_bfloat16 h0 = __float2bfloat16(v00), h1 = __float2bfloat16(v01);
            *reinterpret_cast<uint32_t*>(&g_H[(size_t)r0 * FIELD + n]) =
                ((uint32_t)__bfloat16_as_ushort(h1) << 16) | __bfloat16_as_ushort(h0);
            h0 = __float2bfloat16(v10); h1 = __float2bfloat16(v11);
            *reinterpret_cast<uint32_t*>(&g_H[(size_t)r1 * FIELD + n]) =
                ((uint32_t)__bfloat16_as_ushort(h1) << 16) | __bfloat16_as_ushort(h0);
        }
    }
}

__global__ __launch_bounds__(256)
void gemm2_bulk_kernel(const float* __restrict__ b2)
{
    __shared__ float ssbuf[128];

    const int col0 = blockIdx.x * 128, row0 = blockIdx.y * 128;
    const int tid  = threadIdx.x;
    const int wid  = tid >> 5, lane = tid & 31;
    const int wm   = wid >> 2, wn = wid & 3;
    const int mrow = lane >> 2, qcol = (lane & 3) * 2;

    float acc[4][4][4];
    bulk_mainloop_mma(g_H, g_W2t, row0, col0, acc);

    for (int i = tid; i < 128; i += 256) ssbuf[i] = 0.0f;
    __syncthreads();

#pragma unroll
    for (int mf = 0; mf < 4; mf++) {
        float ss0 = 0.0f, ss1 = 0.0f;
#pragma unroll
        for (int nf = 0; nf < 4; nf++) {
            const int n = col0 + wn * 32 + nf * 8 + qcol;
            const float ba = b2[n], bb = b2[n + 1];
            const float v00 = acc[mf][nf][0] + ba, v01 = acc[mf][nf][1] + bb;
            const float v10 = acc[mf][nf][2] + ba, v11 = acc[mf][nf][3] + bb;
            ss0 = fmaf(v00, v00, fmaf(v01, v01, ss0));
            ss1 = fmaf(v10, v10, fmaf(v11, v11, ss1));
        }
        ss0 += __shfl_xor_sync(0xffffffffu, ss0, 1);
        ss0 += __shfl_xor_sync(0xffffffffu, ss0, 2);
        ss1 += __shfl_xor_sync(0xffffffffu, ss1, 1);
        ss1 += __shfl_xor_sync(0xffffffffu, ss1, 2);
        if ((lane & 3) == 0) {
            atomicAdd(&ssbuf[wm * 64 + mf * 16 + mrow], ss0);
            atomicAdd(&ssbuf[wm * 64 + mf * 16 + mrow + 8], ss1);
        }
    }
    __syncthreads();
    for (int i = tid; i < 128; i += 256)
        g_ssq_part[blockIdx.x][row0 + i] = ssbuf[i];
}

// ---------------------------------------------------------------------------
// Approx importance finalize (vectorized): lane owns 16 consecutive k.
// Two uint4 loads per lane (coalesced 32B), converts in registers, FMA
// against L1-resident g_w2tail. Approx score changes by ~1 ulp only
// (summation order); candidate coverage unaffected (512-rank margin).
// ---------------------------------------------------------------------------
__global__ __launch_bounds__(256) void ssq_finalize_kernel(
    const float* __restrict__ b2)
{
    const int row  = (blockIdx.x * blockDim.x + threadIdx.x) >> 5;
    const int lane = threadIdx.x & 31;
    if (row >= ROWS) return;

    const int k0 = lane * 16;
    const uint4 p0 = *reinterpret_cast<const uint4*>(&g_H[(size_t)row * FIELD + k0]);
    const uint4 p1 = *reinterpret_cast<const uint4*>(&g_H[(size_t)row * FIELD + k0 + 8]);
    const uint32_t w[8] = {p0.x, p0.y, p0.z, p0.w, p1.x, p1.y, p1.z, p1.w};
    float h[16];
#pragma unroll
    for (int q = 0; q < 8; q++) {
        h[2 * q]     = __bfloat162float(__ushort_as_bfloat16((unsigned short)(w[q] & 0xFFFFu)));
        h[2 * q + 1] = __bfloat162float(__ushort_as_bfloat16((unsigned short)(w[q] >> 16)));
    }

    float t0 = 0.0f, t1 = 0.0f, t2 = 0.0f;
#pragma unroll
    for (int j = 0; j < 16; j++) {
        t0 = fmaf(h[j], g_w2tail[0][k0 + j], t0);
        t1 = fmaf(h[j], g_w2tail[1][k0 + j], t1);
        t2 = fmaf(h[j], g_w2tail[2][k0 + j], t2);
    }
#pragma unroll
    for (int o = 16; o; o >>= 1) {
        t0 += __shfl_down_sync(0xffffffffu, t0, o);
        t1 += __shfl_down_sync(0xffffffffu, t1, o);
        t2 += __shfl_down_sync(0xffffffffu, t2, o);
    }
    if (lane == 0) {
        const float v0 = t0 + b2[512], v1 = t1 + b2[513], v2 = t2 + b2[514];
        g_ssq[row] = g_ssq_part[0][row] + g_ssq_part[1][row] +
                     g_ssq_part[2][row] + g_ssq_part[3][row] +
                     v0 * v0 + v1 * v1 + v2 * v2;
    }
}

// ---------------------------------------------------------------------------
// Approx top-CAND via radix select (4 byte-level passes + compaction).
// ---------------------------------------------------------------------------
__global__ __launch_bounds__(1024) void topk_select_kernel()
{
    uint32_t* keys = reinterpret_cast<uint32_t*>(dyn_smem);   // 16384 words
    __shared__ uint32_t hist[256];
    __shared__ uint32_t s_prefix, s_need;
    __shared__ int s_cnt;

    const int b   = blockIdx.x;
    const int tid = threadIdx.x;

    for (int i = tid; i < NPTS; i += 1024) {
        uint32_t u = __float_as_uint(g_ssq[(size_t)b * NPTS + i]);
        keys[i] = (u & 0x80000000u) ? ~u : (u | 0x80000000u);
    }
    __syncthreads();

    uint32_t prefix = 0, need = CAND;
#pragma unroll
    for (int shift = 24; shift >= 0; shift -= 8) {
        if (tid < 256) hist[tid] = 0;
        __syncthreads();
        const uint32_t pmask = (shift == 24) ? 0u : (0xFFFFFFFFu << (shift + 8));
        for (int i = tid; i < NPTS; i += 1024) {
            const uint32_t k = keys[i];
            if ((k & pmask) == prefix)
                atomicAdd(&hist[(k >> shift) & 0xFFu], 1u);
        }
        __syncthreads();
        if (tid == 0) {
            uint32_t cum = 0;
            int bin = 255;
            for (; bin > 0; bin--) {
                if (cum + hist[bin] >= need) break;
                cum += hist[bin];
            }
            s_prefix = prefix | ((uint32_t)bin << shift);
            s_need   = need - cum;
        }
        __syncthreads();
        prefix = s_prefix;
        need   = s_need;
        __syncthreads();
    }

    if (tid == 0) s_cnt = 0;
    __syncthreads();
    const uint32_t T = prefix;
    for (int i = tid; i < NPTS; i += 1024) {
        if (keys[i] > T) {
            const int p = atomicAdd(&s_cnt, 1);
            g_cand[b * CAND + p]     = b * NPTS + i;
            g_cand_idx[b * CAND + p] = i;
        }
    }
    __syncthreads();
    for (int i = tid; i < NPTS; i += 1024) {
        if (keys[i] == T) {
            const int p = atomicAdd(&s_cnt, 1);
            if (p < CAND) {
                g_cand[b * CAND + p]     = b * NPTS + i;
                g_cand_idx[b * CAND + p] = i;
            }
        }
    }
}

// ---------------------------------------------------------------------------
// Exact repair — bit-exact tiled fp32 GEMMs (register-prefetch pipelined).
// ---------------------------------------------------------------------------
#define BM 128
#define BN 64
#define BK 16
#define TM 8
#define TN 4
#define KCH (FIELD / BK)   // 32 chunks

__global__ __launch_bounds__(256) void exactH_kernel(
    const float* __restrict__ coords,
    const float* __restrict__ dens,
    const float* __restrict__ W1,
    const float* __restrict__ b1)
{
    __shared__ float As[BK][BM + 4];
    __shared__ float Bs[BK][BN + 4];
    __shared__ int   rmap[BM];

    const int col0 = blockIdx.x * BN;
    const int row0 = blockIdx.y * BM;
    const int tid  = threadIdx.x;
    const int trow = tid >> 4;
    const int tcol = tid & 15;

    if (tid < BM) rmap[tid] = g_cand[row0 + tid];
    __syncthreads();

    const int ar0 = tid >> 2,            av0 = tid & 3;
    const int ar1 = (tid + 256) >> 2,    av1 = (tid + 256) & 3;
    const int bkk = tid >> 4,            bnn = (tid & 15) * 4;

    float acc[TM][TN];
#pragma unroll
    for (int i = 0; i < TM; i++) {
        const size_t rg = (size_t)rmap[trow * TM + i];
        const float c0 = coords[rg * 2 + 0];
        const float c1 = coords[rg * 2 + 1];
#pragma unroll
        for (int j = 0; j < TN; j++) {
            const int n = col0 + tcol * TN + j;
            float a = fmaf(c0, W1[n], 0.0f);
            a = fmaf(c1, W1[FIELD + n], a);
            acc[i][j] = a;
        }
    }

    float4 aR0 = *reinterpret_cast<const float4*>(
        &dens[(size_t)rmap[ar0] * FIELD + av0 * 4]);
    float4 aR1 = *reinterpret_cast<const float4*>(
        &dens[(size_t)rmap[ar1] * FIELD + av1 * 4]);
    float4 bR  = *reinterpret_cast<const float4*>(
        &W1[(size_t)(2 + bkk) * FIELD + col0 + bnn]);

    for (int c = 0; c < KCH; c++) {
        As[av0 * 4 + 0][ar0] = aR0.x;
        As[av0 * 4 + 1][ar0] = aR0.y;
        As[av0 * 4 + 2][ar0] = aR0.z;
        As[av0 * 4 + 3][ar0] = aR0.w;
        As[av1 * 4 + 0][ar1] = aR1.x;
        As[av1 * 4 + 1][ar1] = aR1.y;
        As[av1 * 4 + 2][ar1] = aR1.z;
        As[av1 * 4 + 3][ar1] = aR1.w;
        Bs[bkk][bnn + 0] = bR.x;
        Bs[bkk][bnn + 1] = bR.y;
        Bs[bkk][bnn + 2] = bR.z;
        Bs[bkk][bnn + 3] = bR.w;
        __syncthreads();

        if (c < KCH - 1) {
            const int k0 = (c + 1) * BK;
            aR0 = *reinterpret_cast<const float4*>(
                &dens[(size_t)rmap[ar0] * FIELD + k0 + av0 * 4]);
            aR1 = *reinterpret_cast<const float4*>(
                &dens[(size_t)rmap[ar1] * FIELD + k0 + av1 * 4]);
            bR  = *reinterpret_cast<const float4*>(
                &W1[(size_t)(2 + k0 + bkk) * FIELD + col0 + bnn]);
        }

#pragma unroll
        for (int kk = 0; kk < BK; kk++) {
            float a[TM], b[TN];
#pragma unroll
            for (int i = 0; i < TM; i++) a[i] = As[kk][trow * TM + i];
#pragma unroll
            for (int j = 0; j < TN; j++) b[j] = Bs[kk][tcol * TN + j];
#pragma unroll
            for (int i = 0; i < TM; i++)
#pragma unroll
                for (int j = 0; j < TN; j++)
                    acc[i][j] = fmaf(a[i], b[j], acc[i][j]);
        }
        __syncthreads();
    }

#pragma unroll
    for (int i = 0; i < TM; i++) {
        const size_t rc = (size_t)row0 + trow * TM + i;
#pragma unroll
        for (int j = 0; j < TN; j++) {
            const int n = col0 + tcol * TN + j;
            const float v = __fadd_rn(acc[i][j], b1[n]);
            g_Hex[rc * FIELD + n] = xla_gelu(v);
        }
    }
}

__global__ __launch_bounds__(256) void exactE_kernel(
    const float* __restrict__ W2, const float* __restrict__ b2)
{
    __shared__ float As[BK][BM + 4];
    __shared__ float Bs[BK][BN + 4];

    const int col0 = blockIdx.x * BN;
    const int row0 = blockIdx.y * BM;
    const int tid  = threadIdx.x;
    const int trow = tid >> 4;
    const int tcol = tid & 15;

    const int ar0 = tid >> 2,            av0 = tid & 3;
    const int ar1 = (tid + 256) >> 2,    av1 = (tid + 256) & 3;
    const int bkk = tid >> 4,            bnn = (tid & 15) * 4;

    float acc[TM][TN];
#pragma unroll
    for (int i = 0; i < TM; i++)
#pragma unroll
        for (int j = 0; j < TN; j++) acc[i][j] = 0.0f;

    float4 aR0 = *reinterpret_cast<const float4*>(
        &g_Hex[(size_t)(row0 + ar0) * FIELD + av0 * 4]);
    float4 aR1 = *reinterpret_cast<const float4*>(
        &g_Hex[(size_t)(row0 + ar1) * FIELD + av1 * 4]);
    float bR[4];
#pragma unroll
    for (int q = 0; q < 4; q++) {
        const int n = col0 + bnn + q;
        bR[q] = (n < OUT_DIM) ? W2[(size_t)bkk * OUT_DIM + n] : 0.0f;
    }

    for (int c = 0; c < KCH; c++) {
        As[av0 * 4 + 0][ar0] = aR0.x;
        As[av0 * 4 + 1][ar0] = aR0.y;
        As[av0 * 4 + 2][ar0] = aR0.z;
        As[av0 * 4 + 3][ar0] = aR0.w;
        As[av1 * 4 + 0][ar1] = aR1.x;
        As[av1 * 4 + 1][ar1] = aR1.y;
        As[av1 * 4 + 2][ar1] = aR1.z;
        As[av1 * 4 + 3][ar1] = aR1.w;
        Bs[bkk][bnn + 0] = bR[0];
        Bs[bkk][bnn + 1] = bR[1];
        Bs[bkk][bnn + 2] = bR[2];
        Bs[bkk][bnn + 3] = bR[3];
        __syncthreads();

        if (c < KCH - 1) {
            const int k0 = (c + 1) * BK;
            aR0 = *reinterpret_cast<const float4*>(
                &g_Hex[(size_t)(row0 + ar0) * FIELD + k0 + av0 * 4]);
            aR1 = *reinterpret_cast<const float4*>(
                &g_Hex[(size_t)(row0 + ar1) * FIELD + k0 + av1 * 4]);
#pragma unroll
            for (int q = 0; q < 4; q++) {
                const int n = col0 + bnn + q;
                bR[q] = (n < OUT_DIM) ? W2[(size_t)(k0 + bkk) * OUT_DIM + n] : 0.0f;
            }
        }

#pragma unroll
        for (int kk = 0; kk < BK; kk++) {
            float a[TM], b[TN];
#pragma unroll
            for (int i = 0; i < TM; i++) a[i] = As[kk][trow * TM + i];
#pragma unroll
            for (int j = 0; j < TN; j++) b[j] = Bs[kk][tcol * TN + j];
#pragma unroll
            for (int i = 0; i < TM; i++)
#pragma unroll
                for (int j = 0; j < TN; j++)
                    acc[i][j] = fmaf(a[i], b[j], acc[i][j]);
        }
        __syncthreads();
    }

#pragma unroll
    for (int i = 0; i < TM; i++) {
        const size_t rc = (size_t)row0 + trow * TM + i;
#pragma unroll
        for (int j = 0; j < TN; j++) {
            const int n = col0 + tcol * TN + j;
            if (n < OUT_DIM)
                g_Eex[rc * OUT_DIM + n] = __fadd_rn(acc[i][j], b2[n]);
        }
    }
}

// Exact norm (XLA warp structure) over compact E — full-grid.
__global__ __launch_bounds__(256) void exact_norm_kernel()
{
    const int rc   = (blockIdx.x * blockDim.x + threadIdx.x) >> 5;
    const int lane = threadIdx.x & 31;
    if (rc >= CTOT) return;

    const float* src = g_Eex + (size_t)rc * OUT_DIM;
    float s = 0.0f;
    for (int c = lane; c < OUT_DIM; c += 32) {
        const float v = src[c];
        s = fmaf(v, v, s);
    }
#pragma unroll
    for (int o = 16; o; o >>= 1)
        s = __fadd_rn(s, __shfl_down_sync(0xffffffffu, s, o));
    if (lane == 0) g_impex[rc] = __fsqrt_rn(s);
}

// Final exact sort of CAND candidates per batch (desc key, asc idx ties).
#define SORTN 2048
__global__ __launch_bounds__(1024) void final_sort_kernel()
{
    __shared__ float key[SORTN];
    __shared__ int   pid[SORTN];
    __shared__ int   pos[SORTN];

    const int b = blockIdx.x;
    for (int i = threadIdx.x; i < SORTN; i += blockDim.x) {
        if (i < CAND) {
            key[i] = g_impex[b * CAND + i];
            pid[i] = g_cand_idx[b * CAND + i];
            pos[i] = b * CAND + i;
        } else {
            key[i] = -INFINITY;
            pid[i] = 0x7fffffff;
            pos[i] = 0;
        }
    }
    __syncthreads();

    for (int k = 2; k <= SORTN; k <<= 1) {
        for (int j = k >> 1; j > 0; j >>= 1) {
            for (int i = threadIdx.x; i < SORTN; i += blockDim.x) {
                const int ixj = i ^ j;
                if (ixj > i) {
                    const bool dirAsc = ((i & k) == 0);
                    float k1 = key[i], k2 = key[ixj];
                    int   p1 = pid[i], p2 = pid[ixj];
                    bool before = (k2 > k1) || (k2 == k1 && p2 < p1);
                    if (before == dirAsc) {
                        key[i] = k2; key[ixj] = k1;
                        pid[i] = p2; pid[ixj] = p1;
                        int t = pos[i]; pos[i] = pos[ixj]; pos[ixj] = t;
                    }
                }
            }
            __syncthreads();
        }
    }
    for (int t = threadIdx.x; t < TOPK; t += blockDim.x)
        g_sel[b * TOPK + t] = pos[t];
}

__global__ __launch_bounds__(128) void gather_kernel(float* __restrict__ out)
{
    const int slot = blockIdx.x;
    const int p    = g_sel[slot];
    const float* row = g_Eex + (size_t)p * OUT_DIM;

    float* poso = out;
    float* st   = out + (size_t)BATCH * TOPK * 2;
    float* wt   = st  + (size_t)BATCH * TOPK * FIELD;

    for (int c = threadIdx.x; c < OUT_DIM; c += blockDim.x) {
        const float v = row[c];
        if (c < 2)                poso[(size_t)slot * 2 + c]          = v;
        else if (c < 2 + FIELD)   st[(size_t)slot * FIELD + (c - 2)]  = v;
        else                      wt[slot]                            = v;
    }
}

// ---------------------------------------------------------------------------
// Launch
// ---------------------------------------------------------------------------
extern "C" void kernel_launch(void* const* d_in, const int* in_sizes, int n_in,
                              void* d_out, int out_size)
{
    const float* coords = (const float*)d_in[0];
    const float* dens   = (const float*)d_in[1];
    const float* W1     = (const float*)d_in[2];
    const float* b1     = (const float*)d_in[3];
    const float* W2     = (const float*)d_in[4];
    const float* b2     = (const float*)d_in[5];
    float* out = (float*)d_out;

    cudaFuncSetAttribute(gemm1_bulk_kernel,
                         cudaFuncAttributeMaxDynamicSharedMemorySize, 2 * STG_BYTES);
    cudaFuncSetAttribute(gemm2_bulk_kernel,
                         cudaFuncAttributeMaxDynamicSharedMemorySize, 2 * STG_BYTES);
    cudaFuncSetAttribute(topk_select_kernel,
                         cudaFuncAttributeMaxDynamicSharedMemorySize,
                         NPTS * sizeof(uint32_t));

    conv_X_kernel<<<(ROWS * FIELD / 4 + 255) / 256, 256>>>(dens);
    conv_W_kernel<<<(FIELD * FIELD + 255) / 256, 256>>>(W1, W2);

    gemm1_bulk_kernel<<<dim3(4, ROWS / 128), 256, 2 * STG_BYTES>>>(coords, W1, b1);
    gemm2_bulk_kernel<<<dim3(4, ROWS / 128), 256, 2 * STG_BYTES>>>(b2);
    ssq_finalize_kernel<<<ROWS / 8, 256>>>(b2);

    topk_select_kernel<<<BATCH, 1024, NPTS * sizeof(uint32_t)>>>();

    exactH_kernel<<<dim3(FIELD / BN, CTOT / BM), 256>>>(coords, dens, W1, b1);
    exactE_kernel<<<dim3((OUT_DIM + BN - 1) / BN, CTOT / BM), 256>>>(W2, b2);
    exact_norm_kernel<<<(CTOT * 32 + 255) / 256, 256>>>();
    final_sort_kernel<<<BATCH, 1024>>>();
    gather_kernel<<<BATCH * TOPK, 128>>>(out);
}

// round 17
// speedup vs baseline: 1.2344x; 1.2344x over previous
#include <cuda_runtime.h>
#include <cuda_bf16.h>
#include <math.h>
#include <stdint.h>

#define BATCH      8
#define NPTS       16384
#define ROWS       (BATCH * NPTS)       // 131072
#define FIELD      512
#define OUT_DIM    515
#define TOPK       1024
#define CAND       1536                 // candidates per batch (margin 512)
#define CTOT       (BATCH * CAND)       // 12288
#define NCHUNK     16                   // FIELD / 32

// ---------------------------------------------------------------------------
// Scratch
// ---------------------------------------------------------------------------
__device__ __nv_bfloat16 g_X[(size_t)ROWS * FIELD];
__device__ __nv_bfloat16 g_H[(size_t)ROWS * FIELD];
__device__ __nv_bfloat16 g_W1t[FIELD * FIELD];      // [n][k] transposed
__device__ __nv_bfloat16 g_W2t[FIELD * FIELD];
__device__ float g_w2tail[3][FIELD];                // W2[:,512..514] transposed
__device__ float g_ssq_part[4][ROWS];               // per N-tile SS partials
__device__ float g_ssq[ROWS];                       // approx importance (SS)
__device__ int   g_cand[CTOT];                      // candidate global rows
__device__ int   g_cand_idx[CTOT];                  // candidate point idx
__device__ float g_Hex[(size_t)CTOT * FIELD];       // exact H (compact)
__device__ float g_Eex[(size_t)CTOT * OUT_DIM];     // exact E (compact)
__device__ float g_impex[CTOT];                     // exact importance
__device__ int   g_sel[BATCH * TOPK];               // compact pos of winners

extern __shared__ char dyn_smem[];   // gemms: 32KB; select: 64KB

// ---------------------------------------------------------------------------
// PTX helpers (base ISA: ldmatrix + mma.sync + cp.async, sm_80+)
// ---------------------------------------------------------------------------
__device__ __forceinline__ uint32_t smem_u32(const void* p)
{
    uint32_t a;
    asm("{ .reg .u64 t; cvta.to.shared.u64 t, %1; cvt.u32.u64 %0, t; }"
        : "=r"(a) : "l"(p));
    return a;
}
__device__ __forceinline__ void ldsm_x4(uint32_t* r, uint32_t addr)
{
    asm volatile("ldmatrix.sync.aligned.m8n8.x4.shared.b16 {%0,%1,%2,%3}, [%4];"
                 : "=r"(r[0]), "=r"(r[1]), "=r"(r[2]), "=r"(r[3]) : "r"(addr));
}
__device__ __forceinline__ void mma_bf16(float* c, const uint32_t* a, const uint32_t* b)
{
    asm volatile(
        "mma.sync.aligned.m16n8k16.row.col.f32.bf16.bf16.f32 "
        "{%0,%1,%2,%3}, {%4,%5,%6,%7}, {%8,%9}, {%0,%1,%2,%3};"
        : "+f"(c[0]), "+f"(c[1]), "+f"(c[2]), "+f"(c[3])
        : "r"(a[0]), "r"(a[1]), "r"(a[2]), "r"(a[3]), "r"(b[0]), "r"(b[1]));
}
__device__ __forceinline__ uint32_t sw64(uint32_t off)
{
    return off ^ ((off >> 3) & 0x30);
}
__device__ __forceinline__ void cp_async16(uint32_t sp, const void* gp)
{
    asm volatile("cp.async.cg.shared.global [%0], [%1], 16;"
                 :: "r"(sp), "l"(gp) : "memory");
}

// ---------------------------------------------------------------------------
// Exact-path math (bit-faithful to reference; proven in R3)
// ---------------------------------------------------------------------------
__device__ __forceinline__ float xla_erf_f32(float x)
{
    x = fminf(fmaxf(x, -4.0f), 4.0f);
    const float z = __fmul_rn(x, x);
    float p = fmaf(z, -2.72614225801306e-10f, 2.77068142495902e-08f);
    p = fmaf(z, p, -2.10102402082508e-06f);
    p = fmaf(z, p, -5.69250639462346e-05f);
    p = fmaf(z, p, -7.34990630326855e-04f);
    p = fmaf(z, p, -2.95459980854025e-03f);
    p = fmaf(z, p, -1.60960333262415e-02f);
    p = __fmul_rn(x, p);
    float q = fmaf(z, -1.45660718464996e-05f, -2.13374055278905e-04f);
    q = fmaf(z, q, -1.68282697438203e-03f);
    q = fmaf(z, q, -7.37332916720468e-03f);
    q = fmaf(z, q, -1.42647390514189e-02f);
    return __fdiv_rn(p, q);
}
__device__ __forceinline__ float xla_gelu(float v)
{
    const float t = __fdiv_rn(v, 1.4142135623730951f);
    const float s = __fadd_rn(xla_erf_f32(t), 1.0f);
    return __fmul_rn(__fmul_rn(v, s), 0.5f);
}

// ---------------------------------------------------------------------------
// Conversion / prep kernels
// ---------------------------------------------------------------------------
__global__ __launch_bounds__(256) void conv_X_kernel(const float* __restrict__ dens)
{
    const size_t base = ((size_t)blockIdx.x * 256 + threadIdx.x) * 4;
    if (base >= (size_t)ROWS * FIELD) return;
    const float4 v = *reinterpret_cast<const float4*>(&dens[base]);
    __nv_bfloat16 h[4];
    h[0] = __float2bfloat16(v.x);
    h[1] = __float2bfloat16(v.y);
    h[2] = __float2bfloat16(v.z);
    h[3] = __float2bfloat16(v.w);
    *reinterpret_cast<uint2*>(&g_X[base]) = *reinterpret_cast<uint2*>(h);
}

__global__ __launch_bounds__(256) void conv_W_kernel(
    const float* __restrict__ W1, const float* __restrict__ W2)
{
    const int id = blockIdx.x * 256 + threadIdx.x;
    if (id >= FIELD * FIELD) return;
    const int n = id >> 9, k = id & 511;
    g_W1t[(size_t)n * FIELD + k] = __float2bfloat16(W1[(size_t)(2 + k) * FIELD + n]);
    g_W2t[(size_t)n * FIELD + k] = __float2bfloat16(W2[(size_t)k * OUT_DIM + n]);
    if (n < 3)
        g_w2tail[n][k] = W2[(size_t)k * OUT_DIM + 512 + n];
}

// ---------------------------------------------------------------------------
// Bulk GEMM: CTA 128x128, BK=32 (16 K-chunks), 8 warps 2(m)x4(n),
// warp tile 64x32, single-pass bf16 mma, cp.async double-buffered.
// ---------------------------------------------------------------------------
#define STG_BYTES 16384

__device__ __forceinline__ void load_tile_async(
    uint32_t dst, const __nv_bfloat16* __restrict__ src,
    int row0, int k0, int tid)
{
#pragma unroll
    for (int s = tid; s < 512; s += 256) {
        const int r = s >> 2, seg = s & 3;
        cp_async16(dst + sw64(r * 64 + seg * 16),
                   &src[(size_t)(row0 + r) * FIELD + k0 + seg * 8]);
    }
}

__device__ __forceinline__ void bulk_mainloop_mma(
    const __nv_bfloat16* __restrict__ A, const __nv_bfloat16* __restrict__ B,
    int row0, int col0, float acc[4][4][4])
{
    const int tid  = threadIdx.x;
    const int wid  = tid >> 5, lane = tid & 31;
    const int wm   = wid >> 2, wn = wid & 3;
    const uint32_t sb = smem_u32(dyn_smem);

    const int a_row = (lane & 7) + ((lane >> 3) & 1) * 8;
    const int a_kof = ((lane >> 4) << 3);
    const int b_row = (lane & 7) + ((lane >> 4) << 3);
    const int b_kof = (((lane >> 3) & 1) << 3);

#pragma unroll
    for (int mf = 0; mf < 4; mf++)
#pragma unroll
        for (int nf = 0; nf < 4; nf++)
#pragma unroll
            for (int q = 0; q < 4; q++) acc[mf][nf][q] = 0.0f;

    {
        load_tile_async(sb +    0, A, row0, 0, tid);
        load_tile_async(sb + 8192, B, col0, 0, tid);
        asm volatile("cp.async.commit_group;" ::: "memory");
    }

    for (int c = 0; c < NCHUNK; c++) {
        if (c < NCHUNK - 1) {
            const uint32_t st = sb + ((c + 1) & 1) * STG_BYTES;
            const int k0 = (c + 1) * 32;
            load_tile_async(st +    0, A, row0, k0, tid);
            load_tile_async(st + 8192, B, col0, k0, tid);
            asm volatile("cp.async.commit_group;" ::: "memory");
            asm volatile("cp.async.wait_group 1;" ::: "memory");
        } else {
            asm volatile("cp.async.wait_group 0;" ::: "memory");
        }
        __syncthreads();

        const uint32_t st = sb + (c & 1) * STG_BYTES;
        const uint32_t aA = st, aB = st + 8192;

#pragma unroll
        for (int kk = 0; kk < 32; kk += 16) {
            uint32_t Af[4][4], Bf[2][4];
#pragma unroll
            for (int mf = 0; mf < 4; mf++) {
                const uint32_t off = sw64(
                    (uint32_t)((wm * 64 + mf * 16 + a_row) * 64 + (kk + a_kof) * 2));
                ldsm_x4(Af[mf], aA + off);
            }
#pragma unroll
            for (int pr = 0; pr < 2; pr++) {
                const uint32_t off = sw64(
                    (uint32_t)((wn * 32 + pr * 16 + b_row) * 64 + (kk + b_kof) * 2));
                ldsm_x4(Bf[pr], aB + off);
            }
#pragma unroll
            for (int mf = 0; mf < 4; mf++)
#pragma unroll
                for (int nf = 0; nf < 4; nf++)
                    mma_bf16(acc[mf][nf], Af[mf], &Bf[nf >> 1][(nf & 1) * 2]);
        }
        __syncthreads();
    }
}

__global__ __launch_bounds__(256)
void gemm1_bulk_kernel(const float* __restrict__ coords,
                       const float* __restrict__ W1,
                       const float* __restrict__ b1)
{
    const int col0 = blockIdx.x * 128, row0 = blockIdx.y * 128;
    const int wid  = threadIdx.x >> 5, lane = threadIdx.x & 31;
    const int wm   = wid >> 2, wn = wid & 3;
    const int mrow = lane >> 2, qcol = (lane & 3) * 2;

    float acc[4][4][4];
    bulk_mainloop_mma(g_X, g_W1t, row0, col0, acc);

#pragma unroll
    for (int mf = 0; mf < 4; mf++) {
        const int r0 = row0 + wm * 64 + mf * 16 + mrow;
        const int r1 = r0 + 8;
        const float c00 = coords[(size_t)r0 * 2], c01 = coords[(size_t)r0 * 2 + 1];
        const float c10 = coords[(size_t)r1 * 2], c11 = coords[(size_t)r1 * 2 + 1];
#pragma unroll
        for (int nf = 0; nf < 4; nf++) {
            const int n = col0 + wn * 32 + nf * 8 + qcol;
            const float w0a = W1[n],     w1a = W1[FIELD + n],     ba = b1[n];
            const float w0b = W1[n + 1], w1b = W1[FIELD + n + 1], bb = b1[n + 1];
            float v00 = xla_gelu(acc[mf][nf][0] + c00 * w0a + c01 * w1a + ba);
            float v01 = xla_gelu(acc[mf][nf][1] + c00 * w0b + c01 * w1b + bb);
            float v10 = xla_gelu(acc[mf][nf][2] + c10 * w0a + c11 * w1a + ba);
            float v11 = xla_gelu(acc[mf][nf][3] + c10 * w0b + c11 * w1b + bb);
            __nv_bfloat16 h0 = __float2bfloat16(v00), h1 = __float2bfloat16(v01);
            *reinterpret_cast<uint32_t*>(&g_H[(size_t)r0 * FIELD + n]) =
                ((uint32_t)__bfloat16_as_ushort(h1) << 16) | __bfloat16_as_ushort(h0);
            h0 = __float2bfloat16(v10); h1 = __float2bfloat16(v11);
            *reinterpret_cast<uint32_t*>(&g_H[(size_t)r1 * FIELD + n]) =
                ((uint32_t)__bfloat16_as_ushort(h1) << 16) | __bfloat16_as_ushort(h0);
        }
    }
}

__global__ __launch_bounds__(256)
void gemm2_bulk_kernel(const float* __restrict__ b2)
{
    __shared__ float ssbuf[128];

    const int col0 = blockIdx.x * 128, row0 = blockIdx.y * 128;
    const int tid  = threadIdx.x;
    const int wid  = tid >> 5, lane = tid & 31;
    const int wm   = wid >> 2, wn = wid & 3;
    const int mrow = lane >> 2, qcol = (lane & 3) * 2;

    float acc[4][4][4];
    bulk_mainloop_mma(g_H, g_W2t, row0, col0, acc);

    for (int i = tid; i < 128; i += 256) ssbuf[i] = 0.0f;
    __syncthreads();

#pragma unroll
    for (int mf = 0; mf < 4; mf++) {
        float ss0 = 0.0f, ss1 = 0.0f;
#pragma unroll
        for (int nf = 0; nf < 4; nf++) {
            const int n = col0 + wn * 32 + nf * 8 + qcol;
            const float ba = b2[n], bb = b2[n + 1];
            const float v00 = acc[mf][nf][0] + ba, v01 = acc[mf][nf][1] + bb;
            const float v10 = acc[mf][nf][2] + ba, v11 = acc[mf][nf][3] + bb;
            ss0 = fmaf(v00, v00, fmaf(v01, v01, ss0));
            ss1 = fmaf(v10, v10, fmaf(v11, v11, ss1));
        }
        ss0 += __shfl_xor_sync(0xffffffffu, ss0, 1);
        ss0 += __shfl_xor_sync(0xffffffffu, ss0, 2);
        ss1 += __shfl_xor_sync(0xffffffffu, ss1, 1);
        ss1 += __shfl_xor_sync(0xffffffffu, ss1, 2);
        if ((lane & 3) == 0) {
            atomicAdd(&ssbuf[wm * 64 + mf * 16 + mrow], ss0);
            atomicAdd(&ssbuf[wm * 64 + mf * 16 + mrow + 8], ss1);
        }
    }
    __syncthreads();
    for (int i = tid; i < 128; i += 256)
        g_ssq_part[blockIdx.x][row0 + i] = ssbuf[i];
}

// ---------------------------------------------------------------------------
// Approx importance finalize: 4 partials + tail (coalesced transposed tail).
// ---------------------------------------------------------------------------
__global__ __launch_bounds__(256) void ssq_finalize_kernel(
    const float* __restrict__ b2)
{
    const int row  = (blockIdx.x * blockDim.x + threadIdx.x) >> 5;
    const int lane = threadIdx.x & 31;
    if (row >= ROWS) return;

    float t0 = 0.0f, t1 = 0.0f, t2 = 0.0f;
    for (int k = lane; k < FIELD; k += 32) {
        const float h = __bfloat162float(g_H[(size_t)row * FIELD + k]);
        t0 = fmaf(h, g_w2tail[0][k], t0);
        t1 = fmaf(h, g_w2tail[1][k], t1);
        t2 = fmaf(h, g_w2tail[2][k], t2);
    }
#pragma unroll
    for (int o = 16; o; o >>= 1) {
        t0 += __shfl_down_sync(0xffffffffu, t0, o);
        t1 += __shfl_down_sync(0xffffffffu, t1, o);
        t2 += __shfl_down_sync(0xffffffffu, t2, o);
    }
    if (lane == 0) {
        const float v0 = t0 + b2[512], v1 = t1 + b2[513], v2 = t2 + b2[514];
        g_ssq[row] = g_ssq_part[0][row] + g_ssq_part[1][row] +
                     g_ssq_part[2][row] + g_ssq_part[3][row] +
                     v0 * v0 + v1 * v1 + v2 * v2;
    }
}

// ---------------------------------------------------------------------------
// Approx top-CAND via radix select (4 byte-level passes + compaction).
// ---------------------------------------------------------------------------
__global__ __launch_bounds__(1024) void topk_select_kernel()
{
    uint32_t* keys = reinterpret_cast<uint32_t*>(dyn_smem);   // 16384 words
    __shared__ uint32_t hist[256];
    __shared__ uint32_t s_prefix, s_need;
    __shared__ int s_cnt;

    const int b   = blockIdx.x;
    const int tid = threadIdx.x;

    for (int i = tid; i < NPTS; i += 1024) {
        uint32_t u = __float_as_uint(g_ssq[(size_t)b * NPTS + i]);
        keys[i] = (u & 0x80000000u) ? ~u : (u | 0x80000000u);
    }
    __syncthreads();

    uint32_t prefix = 0, need = CAND;
#pragma unroll
    for (int shift = 24; shift >= 0; shift -= 8) {
        if (tid < 256) hist[tid] = 0;
        __syncthreads();
        const uint32_t pmask = (shift == 24) ? 0u : (0xFFFFFFFFu << (shift + 8));
        for (int i = tid; i < NPTS; i += 1024) {
            const uint32_t k = keys[i];
            if ((k & pmask) == prefix)
                atomicAdd(&hist[(k >> shift) & 0xFFu], 1u);
        }
        __syncthreads();
        if (tid == 0) {
            uint32_t cum = 0;
            int bin = 255;
            for (; bin > 0; bin--) {
                if (cum + hist[bin] >= need) break;
                cum += hist[bin];
            }
            s_prefix = prefix | ((uint32_t)bin << shift);
            s_need   = need - cum;
        }
        __syncthreads();
        prefix = s_prefix;
        need   = s_need;
        __syncthreads();
    }

    if (tid == 0) s_cnt = 0;
    __syncthreads();
    const uint32_t T = prefix;
    for (int i = tid; i < NPTS; i += 1024) {
        if (keys[i] > T) {
            const int p = atomicAdd(&s_cnt, 1);
            g_cand[b * CAND + p]     = b * NPTS + i;
            g_cand_idx[b * CAND + p] = i;
        }
    }
    __syncthreads();
    for (int i = tid; i < NPTS; i += 1024) {
        if (keys[i] == T) {
            const int p = atomicAdd(&s_cnt, 1);
            if (p < CAND) {
                g_cand[b * CAND + p]     = b * NPTS + i;
                g_cand_idx[b * CAND + p] = i;
            }
        }
    }
}

// ---------------------------------------------------------------------------
// Exact repair — bit-exact tiled fp32 GEMMs (register-prefetch pipelined).
// ---------------------------------------------------------------------------
#define BM 128
#define BN 64
#define BK 16
#define TM 8
#define TN 4
#define KCH (FIELD / BK)   // 32 chunks

__global__ __launch_bounds__(256) void exactH_kernel(
    const float* __restrict__ coords,
    const float* __restrict__ dens,
    const float* __restrict__ W1,
    const float* __restrict__ b1)
{
    __shared__ float As[BK][BM + 4];
    __shared__ float Bs[BK][BN + 4];
    __shared__ int   rmap[BM];

    const int col0 = blockIdx.x * BN;
    const int row0 = blockIdx.y * BM;
    const int tid  = threadIdx.x;
    const int trow = tid >> 4;
    const int tcol = tid & 15;

    if (tid < BM) rmap[tid] = g_cand[row0 + tid];
    __syncthreads();

    const int ar0 = tid >> 2,            av0 = tid & 3;
    const int ar1 = (tid + 256) >> 2,    av1 = (tid + 256) & 3;
    const int bkk = tid >> 4,            bnn = (tid & 15) * 4;

    float acc[TM][TN];
#pragma unroll
    for (int i = 0; i < TM; i++) {
        const size_t rg = (size_t)rmap[trow * TM + i];
        const float c0 = coords[rg * 2 + 0];
        const float c1 = coords[rg * 2 + 1];
#pragma unroll
        for (int j = 0; j < TN; j++) {
            const int n = col0 + tcol * TN + j;
            float a = fmaf(c0, W1[n], 0.0f);
            a = fmaf(c1, W1[FIELD + n], a);
            acc[i][j] = a;
        }
    }

    float4 aR0 = *reinterpret_cast<const float4*>(
        &dens[(size_t)rmap[ar0] * FIELD + av0 * 4]);
    float4 aR1 = *reinterpret_cast<const float4*>(
        &dens[(size_t)rmap[ar1] * FIELD + av1 * 4]);
    float4 bR  = *reinterpret_cast<const float4*>(
        &W1[(size_t)(2 + bkk) * FIELD + col0 + bnn]);

    for (int c = 0; c < KCH; c++) {
        As[av0 * 4 + 0][ar0] = aR0.x;
        As[av0 * 4 + 1][ar0] = aR0.y;
        As[av0 * 4 + 2][ar0] = aR0.z;
        As[av0 * 4 + 3][ar0] = aR0.w;
        As[av1 * 4 + 0][ar1] = aR1.x;
        As[av1 * 4 + 1][ar1] = aR1.y;
        As[av1 * 4 + 2][ar1] = aR1.z;
        As[av1 * 4 + 3][ar1] = aR1.w;
        Bs[bkk][bnn + 0] = bR.x;
        Bs[bkk][bnn + 1] = bR.y;
        Bs[bkk][bnn + 2] = bR.z;
        Bs[bkk][bnn + 3] = bR.w;
        __syncthreads();

        if (c < KCH - 1) {
            const int k0 = (c + 1) * BK;
            aR0 = *reinterpret_cast<const float4*>(
                &dens[(size_t)rmap[ar0] * FIELD + k0 + av0 * 4]);
            aR1 = *reinterpret_cast<const float4*>(
                &dens[(size_t)rmap[ar1] * FIELD + k0 + av1 * 4]);
            bR  = *reinterpret_cast<const float4*>(
                &W1[(size_t)(2 + k0 + bkk) * FIELD + col0 + bnn]);
        }

#pragma unroll
        for (int kk = 0; kk < BK; kk++) {
            float a[TM], b[TN];
#pragma unroll
            for (int i = 0; i < TM; i++) a[i] = As[kk][trow * TM + i];
#pragma unroll
            for (int j = 0; j < TN; j++) b[j] = Bs[kk][tcol * TN + j];
#pragma unroll
            for (int i = 0; i < TM; i++)
#pragma unroll
                for (int j = 0; j < TN; j++)
                    acc[i][j] = fmaf(a[i], b[j], acc[i][j]);
        }
        __syncthreads();
    }

#pragma unroll
    for (int i = 0; i < TM; i++) {
        const size_t rc = (size_t)row0 + trow * TM + i;
#pragma unroll
        for (int j = 0; j < TN; j++) {
            const int n = col0 + tcol * TN + j;
            const float v = __fadd_rn(acc[i][j], b1[n]);
            g_Hex[rc * FIELD + n] = xla_gelu(v);
        }
    }
}

__global__ __launch_bounds__(256) void exactE_kernel(
    const float* __restrict__ W2, const float* __restrict__ b2)
{
    __shared__ float As[BK][BM + 4];
    __shared__ float Bs[BK][BN + 4];

    const int col0 = blockIdx.x * BN;
    const int row0 = blockIdx.y * BM;
    const int tid  = threadIdx.x;
    const int trow = tid >> 4;
    const int tcol = tid & 15;

    const int ar0 = tid >> 2,            av0 = tid & 3;
    const int ar1 = (tid + 256) >> 2,    av1 = (tid + 256) & 3;
    const int bkk = tid >> 4,            bnn = (tid & 15) * 4;

    float acc[TM][TN];
#pragma unroll
    for (int i = 0; i < TM; i++)
#pragma unroll
        for (int j = 0; j < TN; j++) acc[i][j] = 0.0f;

    float4 aR0 = *reinterpret_cast<const float4*>(
        &g_Hex[(size_t)(row0 + ar0) * FIELD + av0 * 4]);
    float4 aR1 = *reinterpret_cast<const float4*>(
        &g_Hex[(size_t)(row0 + ar1) * FIELD + av1 * 4]);
    float bR[4];
#pragma unroll
    for (int q = 0; q < 4; q++) {
        const int n = col0 + bnn + q;
        bR[q] = (n < OUT_DIM) ? W2[(size_t)bkk * OUT_DIM + n] : 0.0f;
    }

    for (int c = 0; c < KCH; c++) {
        As[av0 * 4 + 0][ar0] = aR0.x;
        As[av0 * 4 + 1][ar0] = aR0.y;
        As[av0 * 4 + 2][ar0] = aR0.z;
        As[av0 * 4 + 3][ar0] = aR0.w;
        As[av1 * 4 + 0][ar1] = aR1.x;
        As[av1 * 4 + 1][ar1] = aR1.y;
        As[av1 * 4 + 2][ar1] = aR1.z;
        As[av1 * 4 + 3][ar1] = aR1.w;
        Bs[bkk][bnn + 0] = bR[0];
        Bs[bkk][bnn + 1] = bR[1];
        Bs[bkk][bnn + 2] = bR[2];
        Bs[bkk][bnn + 3] = bR[3];
        __syncthreads();

        if (c < KCH - 1) {
            const int k0 = (c + 1) * BK;
            aR0 = *reinterpret_cast<const float4*>(
                &g_Hex[(size_t)(row0 + ar0) * FIELD + k0 + av0 * 4]);
            aR1 = *reinterpret_cast<const float4*>(
                &g_Hex[(size_t)(row0 + ar1) * FIELD + k0 + av1 * 4]);
#pragma unroll
            for (int q = 0; q < 4; q++) {
                const int n = col0 + bnn + q;
                bR[q] = (n < OUT_DIM) ? W2[(size_t)(k0 + bkk) * OUT_DIM + n] : 0.0f;
            }
        }

#pragma unroll
        for (int kk = 0; kk < BK; kk++) {
            float a[TM], b[TN];
#pragma unroll
            for (int i = 0; i < TM; i++) a[i] = As[kk][trow * TM + i];
#pragma unroll
            for (int j = 0; j < TN; j++) b[j] = Bs[kk][tcol * TN + j];
#pragma unroll
            for (int i = 0; i < TM; i++)
#pragma unroll
                for (int j = 0; j < TN; j++)
                    acc[i][j] = fmaf(a[i], b[j], acc[i][j]);
        }
        __syncthreads();
    }

#pragma unroll
    for (int i = 0; i < TM; i++) {
        const size_t rc = (size_t)row0 + trow * TM + i;
#pragma unroll
        for (int j = 0; j < TN; j++) {
            const int n = col0 + tcol * TN + j;
            if (n < OUT_DIM)
                g_Eex[rc * OUT_DIM + n] = __fadd_rn(acc[i][j], b2[n]);
        }
    }
}

// Exact norm (XLA warp structure) over compact E.
__global__ __launch_bounds__(256) void exact_norm_kernel()
{
    const int rc   = (blockIdx.x * blockDim.x + threadIdx.x) >> 5;
    const int lane = threadIdx.x & 31;
    if (rc >= CTOT) return;

    const float* src = g_Eex + (size_t)rc * OUT_DIM;
    float s = 0.0f;
    for (int c = lane; c < OUT_DIM; c += 32) {
        const float v = src[c];
        s = fmaf(v, v, s);
    }
#pragma unroll
    for (int o = 16; o; o >>= 1)
        s = __fadd_rn(s, __shfl_down_sync(0xffffffffu, s, o));
    if (lane == 0) g_impex[rc] = __fsqrt_rn(s);
}

// Final exact sort of CAND candidates per batch (desc key, asc idx ties).
#define SORTN 2048
__global__ __launch_bounds__(1024) void final_sort_kernel()
{
    __shared__ float key[SORTN];
    __shared__ int   pid[SORTN];
    __shared__ int   pos[SORTN];

    const int b = blockIdx.x;
    for (int i = threadIdx.x; i < SORTN; i += blockDim.x) {
        if (i < CAND) {
            key[i] = g_impex[b * CAND + i];
            pid[i] = g_cand_idx[b * CAND + i];
            pos[i] = b * CAND + i;
        } else {
            key[i] = -INFINITY;
            pid[i] = 0x7fffffff;
            pos[i] = 0;
        }
    }
    __syncthreads();

    for (int k = 2; k <= SORTN; k <<= 1) {
        for (int j = k >> 1; j > 0; j >>= 1) {
            for (int i = threadIdx.x; i < SORTN; i += blockDim.x) {
                const int ixj = i ^ j;
                if (ixj > i) {
                    const bool dirAsc = ((i & k) == 0);
                    float k1 = key[i], k2 = key[ixj];
                    int   p1 = pid[i], p2 = pid[ixj];
                    bool before = (k2 > k1) || (k2 == k1 && p2 < p1);
                    if (before == dirAsc) {
                        key[i] = k2; key[ixj] = k1;
                        pid[i] = p2; pid[ixj] = p1;
                        int t = pos[i]; pos[i] = pos[ixj]; pos[ixj] = t;
                    }
                }
            }
            __syncthreads();
        }
    }
    for (int t = threadIdx.x; t < TOPK; t += blockDim.x)
        g_sel[b * TOPK + t] = pos[t];
}

__global__ __launch_bounds__(128) void gather_kernel(float* __restrict__ out)
{
    const int slot = blockIdx.x;
    const int p    = g_sel[slot];
    const float* row = g_Eex + (size_t)p * OUT_DIM;

    float* poso = out;
    float* st   = out + (size_t)BATCH * TOPK * 2;
    float* wt   = st  + (size_t)BATCH * TOPK * FIELD;

    for (int c = threadIdx.x; c < OUT_DIM; c += blockDim.x) {
        const float v = row[c];
        if (c < 2)                poso[(size_t)slot * 2 + c]          = v;
        else if (c < 2 + FIELD)   st[(size_t)slot * FIELD + (c - 2)]  = v;
        else                      wt[slot]                            = v;
    }
}

// ---------------------------------------------------------------------------
// Launch
// ---------------------------------------------------------------------------
extern "C" void kernel_launch(void* const* d_in, const int* in_sizes, int n_in,
                              void* d_out, int out_size)
{
    const float* coords = (const float*)d_in[0];
    const float* dens   = (const float*)d_in[1];
    const float* W1     = (const float*)d_in[2];
    const float* b1     = (const float*)d_in[3];
    const float* W2     = (const float*)d_in[4];
    const float* b2     = (const float*)d_in[5];
    float* out = (float*)d_out;

    cudaFuncSetAttribute(gemm1_bulk_kernel,
                         cudaFuncAttributeMaxDynamicSharedMemorySize, 2 * STG_BYTES);
    cudaFuncSetAttribute(gemm2_bulk_kernel,
                         cudaFuncAttributeMaxDynamicSharedMemorySize, 2 * STG_BYTES);
    cudaFuncSetAttribute(topk_select_kernel,
                         cudaFuncAttributeMaxDynamicSharedMemorySize,
                         NPTS * sizeof(uint32_t));

    conv_X_kernel<<<(ROWS * FIELD / 4 + 255) / 256, 256>>>(dens);
    conv_W_kernel<<<(FIELD * FIELD + 255) / 256, 256>>>(W1, W2);

    gemm1_bulk_kernel<<<dim3(4, ROWS / 128), 256, 2 * STG_BYTES>>>(coords, W1, b1);
    gemm2_bulk_kernel<<<dim3(4, ROWS / 128), 256, 2 * STG_BYTES>>>(b2);
    ssq_finalize_kernel<<<ROWS / 8, 256>>>(b2);

    topk_select_kernel<<<BATCH, 1024, NPTS * sizeof(uint32_t)>>>();

    exactH_kernel<<<dim3(FIELD / BN, CTOT / BM), 256>>>(coords, dens, W1, b1);
    exactE_kernel<<<dim3((OUT_DIM + BN - 1) / BN, CTOT / BM), 256>>>(W2, b2);
    exact_norm_kernel<<<(CTOT * 32 + 255) / 256, 256>>>();
    final_sort_kernel<<<BATCH, 1024>>>();
    gather_kernel<<<BATCH * TOPK, 128>>>(out);
}